// round 1
// baseline (speedup 1.0000x reference)
#include <cuda_runtime.h>
#include <math.h>

#define NN 100000
#define EE 1600000
#define HH 32

// ---------------- device scratch (static, no runtime allocation) ----------------
__device__ float    g_emb[NN * HH];     // raw encoder output, then BN-normalized in place
__device__ float    g_A[NN * HH];       // emb @ (W_top - W_bot)          (gathered at dst)
__device__ float    g_B[NN * HH];       // emb @ W_bot + b_msg            (gathered at src)
__device__ unsigned g_aggk[NN * HH];    // monotonic-encoded float max keys
__device__ double   g_stats[4 * HH];    // [0:32) sum_all [32:64) sq_all [64:96) sum_conv [96:128) sq_conv

// ---------------- helpers ----------------
__device__ __forceinline__ unsigned f2k(float f) {
    unsigned u = __float_as_uint(f);
    return (u & 0x80000000u) ? ~u : (u | 0x80000000u);
}
__device__ __forceinline__ float k2f(unsigned u) {
    return (u & 0x80000000u) ? __uint_as_float(u ^ 0x80000000u) : __uint_as_float(~u);
}
__device__ __forceinline__ float eluf(float x) { return x > 0.f ? x : expm1f(x); }

// key encoding of -inf: u=0xFF800000 (negative) -> ~u = 0x007FFFFF
#define NEG_INF_KEY 0x007FFFFFu

// ---------------- K0: init keys + zero stats ----------------
__global__ void k_init() {
    int stride = gridDim.x * blockDim.x;
    int i0 = blockIdx.x * blockDim.x + threadIdx.x;
    for (int t = i0; t < NN * HH; t += stride) g_aggk[t] = NEG_INF_KEY;
    if (i0 < 4 * HH) g_stats[i0] = 0.0;
}

// ---------------- K1: node encoder (cont MLP + cat embeddings + enc MLP), raw emb ----------------
__global__ void k_encode(const float* __restrict__ x_cont, const int* __restrict__ x_cat,
                         const float* __restrict__ Wc, const float* __restrict__ bc,
                         const float* __restrict__ Tch, const float* __restrict__ Tpdg,
                         const float* __restrict__ Tpv,
                         const float* __restrict__ Wcat, const float* __restrict__ bcat,
                         const float* __restrict__ Wenc, const float* __restrict__ benc) {
    __shared__ float sWc[96], sbc[16], sTch[24], sTpdg[56], sTpv[64];
    __shared__ float sWcat[384], sbcat[16], sWenc[1024], sbenc[32];
    int tid = threadIdx.x;
    for (int i = tid; i < 96;  i += blockDim.x) sWc[i]  = Wc[i];
    for (int i = tid; i < 16;  i += blockDim.x) { sbc[i] = bc[i]; sbcat[i] = bcat[i]; }
    for (int i = tid; i < 24;  i += blockDim.x) sTch[i] = Tch[i];
    for (int i = tid; i < 56;  i += blockDim.x) sTpdg[i] = Tpdg[i];
    for (int i = tid; i < 64;  i += blockDim.x) sTpv[i] = Tpv[i];
    for (int i = tid; i < 384; i += blockDim.x) sWcat[i] = Wcat[i];
    for (int i = tid; i < 1024; i += blockDim.x) sWenc[i] = Wenc[i];
    for (int i = tid; i < 32;  i += blockDim.x) sbenc[i] = benc[i];
    __syncthreads();

    int n = blockIdx.x * blockDim.x + tid;
    if (n >= NN) return;

    float xc[6];
#pragma unroll
    for (int j = 0; j < 6; j++) xc[j] = x_cont[n * 6 + j];

    // continuous branch -> 16
    float ec[16];
#pragma unroll
    for (int h = 0; h < 16; h++) {
        float a = sbc[h];
#pragma unroll
        for (int j = 0; j < 6; j++) a += xc[j] * sWc[j * 16 + h];
        ec[h] = eluf(a);
    }

    // categorical branch
    int pdg = x_cat[n * 3 + 0], chrg = x_cat[n * 3 + 1], pv = x_cat[n * 3 + 2];
    int ap = pdg < 0 ? -pdg : pdg;
    int pi = (ap == 1) ? 0 : (ap == 2) ? 1 : (ap == 11) ? 2 : (ap == 13) ? 3
           : (ap == 22) ? 4 : (ap == 130) ? 5 : 6;

    float in24[24];
#pragma unroll
    for (int j = 0; j < 8; j++) {
        in24[j]      = sTch[(chrg + 1) * 8 + j];
        in24[8 + j]  = sTpdg[pi * 8 + j];
        in24[16 + j] = sTpv[pv * 8 + j];
    }

    float in32[32];
#pragma unroll
    for (int h = 0; h < 16; h++) {
        float a = sbcat[h];
#pragma unroll
        for (int j = 0; j < 24; j++) a += in24[j] * sWcat[j * 16 + h];
        in32[h]      = eluf(a);   // emb_cat first
        in32[16 + h] = ec[h];     // emb_cont second
    }

#pragma unroll
    for (int h = 0; h < 32; h++) {
        float a = sbenc[h];
#pragma unroll
        for (int j = 0; j < 32; j++) a += in32[j] * sWenc[j * 32 + h];
        g_emb[n * 32 + h] = eluf(a);
    }
}

// ---------------- K2/K5: per-channel sum & sumsq (lane == channel) ----------------
// mode 0: over g_emb (raw)  -> g_stats[0..63]
// mode 1: over decoded g_aggk (nonfinite->0) -> g_stats[64..127]
__global__ void k_stats(int mode) {
    int lane = threadIdx.x & 31;
    float s = 0.f, q = 0.f;
    int stride = gridDim.x * blockDim.x;             // multiple of 32 -> lane keeps its channel
    for (int t = blockIdx.x * blockDim.x + threadIdx.x; t < NN * HH; t += stride) {
        float v;
        if (mode == 0) v = g_emb[t];
        else { float f = k2f(g_aggk[t]); v = isfinite(f) ? f : 0.f; }
        s += v; q += v * v;
    }
    __shared__ float ss[32], sq[32];
    if (threadIdx.x < 32) { ss[threadIdx.x] = 0.f; sq[threadIdx.x] = 0.f; }
    __syncthreads();
    atomicAdd(&ss[lane], s);
    atomicAdd(&sq[lane], q);
    __syncthreads();
    if (threadIdx.x < 32) {
        int off = mode ? 64 : 0;
        atomicAdd(&g_stats[off + threadIdx.x],      (double)ss[threadIdx.x]);
        atomicAdd(&g_stats[off + 32 + threadIdx.x], (double)sq[threadIdx.x]);
    }
}

// ---------------- K3: BN-apply in place + precompute per-node A, B ----------------
__global__ void k_node2(const float* __restrict__ ga, const float* __restrict__ bea,
                        const float* __restrict__ Wm, const float* __restrict__ bm) {
    __shared__ float sWA[1024], sWB[1024];
    __shared__ float smu[32], sinv[32], sg[32], sbe[32], sbm[32];
    int tid = threadIdx.x;
    for (int i = tid; i < 1024; i += blockDim.x) {
        float wt = Wm[i], wb = Wm[1024 + i];
        sWA[i] = wt - wb;   // (W_top - W_bot)[k][h]
        sWB[i] = wb;        // W_bot[k][h]
    }
    if (tid < 32) {
        double mu  = g_stats[tid] * (1.0 / NN);
        double var = g_stats[32 + tid] * (1.0 / NN) - mu * mu;
        smu[tid]  = (float)mu;
        sinv[tid] = rsqrtf((float)var + 1e-5f);
        sg[tid] = ga[tid]; sbe[tid] = bea[tid]; sbm[tid] = bm[tid];
    }
    __syncthreads();

    int n = blockIdx.x * blockDim.x + tid;
    if (n >= NN) return;

    float e[32];
#pragma unroll
    for (int h = 0; h < 32; h++) {
        float v = g_emb[n * 32 + h];
        v = (v - smu[h]) * sinv[h] * sg[h] + sbe[h];
        e[h] = v;
        g_emb[n * 32 + h] = v;   // normalized emb for residual
    }
#pragma unroll
    for (int h = 0; h < 32; h++) {
        float a = 0.f, b = sbm[h];
#pragma unroll
        for (int k = 0; k < 32; k++) {
            a += e[k] * sWA[k * 32 + h];
            b += e[k] * sWB[k * 32 + h];
        }
        g_A[n * 32 + h] = a;
        g_B[n * 32 + h] = b;
    }
}

// ---------------- K4: edges -> atomic max (msg = A[dst] + B[src]) ----------------
__global__ void k_edge(const int* __restrict__ ei) {
    int lane = threadIdx.x & 31;
    int warp = (blockIdx.x * blockDim.x + threadIdx.x) >> 5;
    int nw = (gridDim.x * blockDim.x) >> 5;
    const int* __restrict__ sp = ei;
    const int* __restrict__ dp = ei + EE;
    for (int e = warp; e < EE; e += nw) {
        int s = sp[e], d = dp[e];
        float v = g_A[d * 32 + lane] + g_B[s * 32 + lane];
        atomicMax(&g_aggk[d * 32 + lane], f2k(v));
    }
}

// ---------------- K6: BN(agg) residual + output MLP ----------------
__global__ void k_final(const float* __restrict__ gc, const float* __restrict__ bec,
                        const float* __restrict__ W1, const float* __restrict__ b1,
                        const float* __restrict__ W2, const float* __restrict__ b2,
                        float* __restrict__ out) {
    __shared__ float sW1[512], sb1[16], sW2[16];
    __shared__ float smu[32], sinv[32], sg[32], sbe[32];
    __shared__ float sb2;
    int tid = threadIdx.x;
    for (int i = tid; i < 512; i += blockDim.x) sW1[i] = W1[i];
    if (tid < 16) { sb1[tid] = b1[tid]; sW2[tid] = W2[tid]; }
    if (tid == 0) sb2 = b2[0];
    if (tid < 32) {
        double mu  = g_stats[64 + tid] * (1.0 / NN);
        double var = g_stats[96 + tid] * (1.0 / NN) - mu * mu;
        smu[tid]  = (float)mu;
        sinv[tid] = rsqrtf((float)var + 1e-5f);
        sg[tid] = gc[tid]; sbe[tid] = bec[tid];
    }
    __syncthreads();

    int n = blockIdx.x * blockDim.x + tid;
    if (n >= NN) return;

    float ef[32];
#pragma unroll
    for (int h = 0; h < 32; h++) {
        float f = k2f(g_aggk[n * 32 + h]);
        if (!isfinite(f)) f = 0.f;
        ef[h] = g_emb[n * 32 + h] + (f - smu[h]) * sinv[h] * sg[h] + sbe[h];
    }

    float o = sb2;
#pragma unroll
    for (int h = 0; h < 16; h++) {
        float a = sb1[h];
#pragma unroll
        for (int j = 0; j < 32; j++) a += ef[j] * sW1[j * 16 + h];
        o += eluf(a) * sW2[h];
    }
    out[n] = o;
}

// ---------------- launch ----------------
extern "C" void kernel_launch(void* const* d_in, const int* in_sizes, int n_in,
                              void* d_out, int out_size) {
    const float* x_cont = (const float*)d_in[0];
    const int*   x_cat  = (const int*)d_in[1];
    const int*   eidx   = (const int*)d_in[2];
    // d_in[3] = batch (unused, single graph)
    const float* W_cont = (const float*)d_in[4];
    const float* b_cont = (const float*)d_in[5];
    const float* T_chrg = (const float*)d_in[6];
    const float* T_pdg  = (const float*)d_in[7];
    const float* T_pv   = (const float*)d_in[8];
    const float* W_cat  = (const float*)d_in[9];
    const float* b_cat  = (const float*)d_in[10];
    const float* W_enc  = (const float*)d_in[11];
    const float* b_enc  = (const float*)d_in[12];
    const float* g_all  = (const float*)d_in[13];
    const float* be_all = (const float*)d_in[14];
    const float* W_msg  = (const float*)d_in[15];
    const float* b_msg  = (const float*)d_in[16];
    const float* g_conv = (const float*)d_in[17];
    const float* be_conv= (const float*)d_in[18];
    const float* W_out1 = (const float*)d_in[19];
    const float* b_out1 = (const float*)d_in[20];
    const float* W_out2 = (const float*)d_in[21];
    const float* b_out2 = (const float*)d_in[22];
    float* out = (float*)d_out;

    const int TB = 256;
    const int nodeBlocks = (NN + TB - 1) / TB;

    k_init<<<2048, TB>>>();
    k_encode<<<nodeBlocks, TB>>>(x_cont, x_cat, W_cont, b_cont, T_chrg, T_pdg, T_pv,
                                 W_cat, b_cat, W_enc, b_enc);
    k_stats<<<1024, TB>>>(0);
    k_node2<<<nodeBlocks, TB>>>(g_all, be_all, W_msg, b_msg);
    k_edge<<<4096, TB>>>(eidx);
    k_stats<<<1024, TB>>>(1);
    k_final<<<nodeBlocks, TB>>>(g_conv, be_conv, W_out1, b_out1, W_out2, b_out2, out);
}

// round 11
// speedup vs baseline: 1.2407x; 1.2407x over previous
#include <cuda_runtime.h>
#include <math.h>

#define NN 100000
#define EE 1600000
#define HH 32
#define SCAN_T 1024
#define SCAN_B 98   // ceil(100000/1024)

// ---------------- device scratch ----------------
__device__ float  g_emb[NN * HH];    // RAW encoder output (pre-BN)
__device__ float  g_A[NN * HH];      // BN-folded: contributes at dst
__device__ float  g_B[NN * HH];      // BN-folded + b_msg: contributes at src
__device__ float  g_agg[NN * HH];    // segment-max result (post-where)
__device__ int    g_cnt[NN];
__device__ int    g_off[NN];
__device__ int    g_cur[NN];
__device__ int    g_bsum[128];
__device__ int    g_ssrc[EE];
__device__ double g_stats[128];      // [0:32) sum_emb [32:64) sq_emb [64:96) sum_agg [96:128) sq_agg

// ---------------- helpers ----------------
__device__ __forceinline__ float eluf(float x) { return x > 0.f ? x : expm1f(x); }

__device__ __forceinline__ unsigned long long pk2(float lo, float hi) {
    unsigned long long r;
    asm("mov.b64 %0,{%1,%2};" : "=l"(r) : "f"(lo), "f"(hi));
    return r;
}
__device__ __forceinline__ void upk2(unsigned long long v, float& lo, float& hi) {
    asm("mov.b64 {%0,%1},%2;" : "=f"(lo), "=f"(hi) : "l"(v));
}
__device__ __forceinline__ unsigned long long fma2(unsigned long long a, unsigned long long b,
                                                   unsigned long long c) {
    unsigned long long d;
    asm("fma.rn.f32x2 %0,%1,%2,%3;" : "=l"(d) : "l"(a), "l"(b), "l"(c));
    return d;
}

// ---------------- K0: init ----------------
__global__ void k_init() {
    int i = blockIdx.x * blockDim.x + threadIdx.x;
    if (i < NN) g_cnt[i] = 0;
    if (i < 128) g_stats[i] = 0.0;
}

// ---------------- K1: node encoder -> RAW emb ----------------
__global__ void k_encode(const float* __restrict__ x_cont, const int* __restrict__ x_cat,
                         const float* __restrict__ Wc, const float* __restrict__ bc,
                         const float* __restrict__ Tch, const float* __restrict__ Tpdg,
                         const float* __restrict__ Tpv,
                         const float* __restrict__ Wcat, const float* __restrict__ bcat,
                         const float* __restrict__ Wenc, const float* __restrict__ benc) {
    __shared__ float sWc[96], sbc[16], sTch[24], sTpdg[56], sTpv[64];
    __shared__ float sWcat[384], sbcat[16], sWenc[1024], sbenc[32];
    int tid = threadIdx.x;
    for (int i = tid; i < 96;  i += blockDim.x) sWc[i]  = Wc[i];
    for (int i = tid; i < 16;  i += blockDim.x) { sbc[i] = bc[i]; sbcat[i] = bcat[i]; }
    for (int i = tid; i < 24;  i += blockDim.x) sTch[i] = Tch[i];
    for (int i = tid; i < 56;  i += blockDim.x) sTpdg[i] = Tpdg[i];
    for (int i = tid; i < 64;  i += blockDim.x) sTpv[i] = Tpv[i];
    for (int i = tid; i < 384; i += blockDim.x) sWcat[i] = Wcat[i];
    for (int i = tid; i < 1024; i += blockDim.x) sWenc[i] = Wenc[i];
    for (int i = tid; i < 32;  i += blockDim.x) sbenc[i] = benc[i];
    __syncthreads();

    int n = blockIdx.x * blockDim.x + tid;
    if (n >= NN) return;

    float xc[6];
#pragma unroll
    for (int j = 0; j < 6; j++) xc[j] = x_cont[n * 6 + j];

    // continuous branch -> 16 (small, scalar)
    float ec[16];
#pragma unroll
    for (int h = 0; h < 16; h++) {
        float a = sbc[h];
#pragma unroll
        for (int j = 0; j < 6; j++) a += xc[j] * sWc[j * 16 + h];
        ec[h] = eluf(a);
    }

    // categorical branch
    int pdg = x_cat[n * 3 + 0], chrg = x_cat[n * 3 + 1], pv = x_cat[n * 3 + 2];
    int ap = pdg < 0 ? -pdg : pdg;
    int pi = (ap == 1) ? 0 : (ap == 2) ? 1 : (ap == 11) ? 2 : (ap == 13) ? 3
           : (ap == 22) ? 4 : (ap == 130) ? 5 : 6;

    float in24[24];
#pragma unroll
    for (int j = 0; j < 8; j++) {
        in24[j]      = sTch[(chrg + 1) * 8 + j];
        in24[8 + j]  = sTpdg[pi * 8 + j];
        in24[16 + j] = sTpv[pv * 8 + j];
    }

    // cat layer 24 -> 16: float4 LDS + f32x2
    float in32[32];
#pragma unroll
    for (int h4 = 0; h4 < 16; h4 += 4) {
        unsigned long long aL = pk2(sbcat[h4],     sbcat[h4 + 1]);
        unsigned long long aH = pk2(sbcat[h4 + 2], sbcat[h4 + 3]);
#pragma unroll
        for (int j = 0; j < 24; j++) {
            float4 w = *(const float4*)&sWcat[j * 16 + h4];
            unsigned long long e2 = pk2(in24[j], in24[j]);
            aL = fma2(e2, pk2(w.x, w.y), aL);
            aH = fma2(e2, pk2(w.z, w.w), aH);
        }
        float v0, v1, v2, v3;
        upk2(aL, v0, v1); upk2(aH, v2, v3);
        in32[h4] = eluf(v0); in32[h4 + 1] = eluf(v1);
        in32[h4 + 2] = eluf(v2); in32[h4 + 3] = eluf(v3);
    }
#pragma unroll
    for (int h = 0; h < 16; h++) in32[16 + h] = ec[h];

    // enc layer 32 -> 32: float4 LDS + f32x2
#pragma unroll
    for (int h4 = 0; h4 < 32; h4 += 4) {
        unsigned long long aL = pk2(sbenc[h4],     sbenc[h4 + 1]);
        unsigned long long aH = pk2(sbenc[h4 + 2], sbenc[h4 + 3]);
#pragma unroll
        for (int k = 0; k < 32; k++) {
            float4 w = *(const float4*)&sWenc[k * 32 + h4];
            unsigned long long e2 = pk2(in32[k], in32[k]);
            aL = fma2(e2, pk2(w.x, w.y), aL);
            aH = fma2(e2, pk2(w.z, w.w), aH);
        }
        float v0, v1, v2, v3;
        upk2(aL, v0, v1); upk2(aH, v2, v3);
        float4 o = make_float4(eluf(v0), eluf(v1), eluf(v2), eluf(v3));
        *(float4*)&g_emb[n * 32 + h4] = o;
    }
}

// ---------------- K2: histogram of dst ----------------
__global__ void k_hist(const int* __restrict__ ei) {
    int e = blockIdx.x * blockDim.x + threadIdx.x;
    if (e < EE) atomicAdd(&g_cnt[ei[EE + e]], 1);
}

// ---------------- scan (3 phases) ----------------
__global__ void k_scan_a() {
    __shared__ int sc[SCAN_T];
    int b = blockIdx.x, t = threadIdx.x;
    int i = b * SCAN_T + t;
    sc[t] = (i < NN) ? g_cnt[i] : 0;
    __syncthreads();
    for (int s = SCAN_T / 2; s > 0; s >>= 1) {
        if (t < s) sc[t] += sc[t + s];
        __syncthreads();
    }
    if (t == 0) g_bsum[b] = sc[0];
}
__global__ void k_scan_b() {
    if (threadIdx.x == 0) {
        int run = 0;
        for (int i = 0; i < SCAN_B; i++) { int v = g_bsum[i]; g_bsum[i] = run; run += v; }
    }
}
__global__ void k_scan_c() {
    __shared__ int sc[SCAN_T];
    int b = blockIdx.x, t = threadIdx.x;
    int i = b * SCAN_T + t;
    int v = (i < NN) ? g_cnt[i] : 0;
    sc[t] = v;
    __syncthreads();
    for (int off = 1; off < SCAN_T; off <<= 1) {
        int x = (t >= off) ? sc[t - off] : 0;
        __syncthreads();
        sc[t] += x;
        __syncthreads();
    }
    if (i < NN) {
        int excl = sc[t] - v + g_bsum[b];
        g_off[i] = excl;
        g_cur[i] = excl;
    }
}

// ---------------- K3: scatter src by dst ----------------
__global__ void k_scatter(const int* __restrict__ ei) {
    int e = blockIdx.x * blockDim.x + threadIdx.x;
    if (e < EE) {
        int s = ei[e], d = ei[EE + e];
        int pos = atomicAdd(&g_cur[d], 1);
        g_ssrc[pos] = s;
    }
}

// ---------------- K4: per-channel stats of raw emb (lane==channel) ----------------
__global__ void k_stats0() {
    int lane = threadIdx.x & 31;
    float s = 0.f, q = 0.f;
    int stride = gridDim.x * blockDim.x;  // multiple of 32
    for (int t = blockIdx.x * blockDim.x + threadIdx.x; t < NN * HH; t += stride) {
        float v = g_emb[t];
        s += v; q += v * v;
    }
    __shared__ float ss[32], sq[32];
    if (threadIdx.x < 32) { ss[threadIdx.x] = 0.f; sq[threadIdx.x] = 0.f; }
    __syncthreads();
    atomicAdd(&ss[lane], s);
    atomicAdd(&sq[lane], q);
    __syncthreads();
    if (threadIdx.x < 32) {
        atomicAdd(&g_stats[threadIdx.x],      (double)ss[threadIdx.x]);
        atomicAdd(&g_stats[32 + threadIdx.x], (double)sq[threadIdx.x]);
    }
}

// ---------------- K5: A,B with BN folded into weights (reads RAW emb) ----------------
__global__ void k_node2(const float* __restrict__ ga, const float* __restrict__ bea,
                        const float* __restrict__ Wm, const float* __restrict__ bm) {
    __shared__ float sWA[1024], sWB[1024];   // scale-folded weights
    __shared__ float sCA[32], sCB[32];       // shift-folded constants
    __shared__ float sScale[32], sShift[32];
    int tid = threadIdx.x;
    if (tid < 32) {
        double mu  = g_stats[tid] * (1.0 / NN);
        double var = g_stats[32 + tid] * (1.0 / NN) - mu * mu;
        float inv = rsqrtf((float)var + 1e-5f);
        float sc = inv * ga[tid];
        sScale[tid] = sc;
        sShift[tid] = bea[tid] - (float)mu * sc;   // normalized e_k = raw*sc + shift
    }
    __syncthreads();
    for (int i = tid; i < 1024; i += blockDim.x) {
        int k = i >> 5;
        float wt = Wm[i], wb = Wm[1024 + i];
        sWA[i] = sScale[k] * (wt - wb);
        sWB[i] = sScale[k] * wb;
    }
    if (tid < 32) {
        float ca = 0.f, cb = bm[tid];
#pragma unroll
        for (int k = 0; k < 32; k++) {
            float wt = Wm[k * 32 + tid], wb = Wm[1024 + k * 32 + tid];
            ca += sShift[k] * (wt - wb);
            cb += sShift[k] * wb;
        }
        sCA[tid] = ca; sCB[tid] = cb;
    }
    __syncthreads();

    int n = blockIdx.x * blockDim.x + tid;
    if (n >= NN) return;

    float e[32];
#pragma unroll
    for (int j = 0; j < 32; j += 4) {
        float4 v = *(const float4*)&g_emb[n * 32 + j];
        e[j] = v.x; e[j + 1] = v.y; e[j + 2] = v.z; e[j + 3] = v.w;
    }

#pragma unroll
    for (int h4 = 0; h4 < 32; h4 += 4) {
        unsigned long long aL = pk2(sCA[h4], sCA[h4 + 1]);
        unsigned long long aH = pk2(sCA[h4 + 2], sCA[h4 + 3]);
        unsigned long long bL = pk2(sCB[h4], sCB[h4 + 1]);
        unsigned long long bH = pk2(sCB[h4 + 2], sCB[h4 + 3]);
#pragma unroll
        for (int k = 0; k < 32; k++) {
            unsigned long long e2 = pk2(e[k], e[k]);
            float4 wa = *(const float4*)&sWA[k * 32 + h4];
            float4 wb = *(const float4*)&sWB[k * 32 + h4];
            aL = fma2(e2, pk2(wa.x, wa.y), aL);
            aH = fma2(e2, pk2(wa.z, wa.w), aH);
            bL = fma2(e2, pk2(wb.x, wb.y), bL);
            bH = fma2(e2, pk2(wb.z, wb.w), bH);
        }
        float a0, a1, a2, a3, b0, b1, b2, b3;
        upk2(aL, a0, a1); upk2(aH, a2, a3);
        upk2(bL, b0, b1); upk2(bH, b2, b3);
        *(float4*)&g_A[n * 32 + h4] = make_float4(a0, a1, a2, a3);
        *(float4*)&g_B[n * 32 + h4] = make_float4(b0, b1, b2, b3);
    }
}

// ---------------- K6: segmented max (warp per dst) + fused agg stats ----------------
__global__ void k_segmax() {
    int lane = threadIdx.x & 31;
    int warp = (blockIdx.x * blockDim.x + threadIdx.x) >> 5;
    int nw = (gridDim.x * blockDim.x) >> 5;

    __shared__ float ss[32], sq[32];
    if (threadIdx.x < 32) { ss[threadIdx.x] = 0.f; sq[threadIdx.x] = 0.f; }
    __syncthreads();

    float s = 0.f, q = 0.f;
    const float NEGINF = -__int_as_float(0x7f800000);

    for (int d = warp; d < NN; d += nw) {
        int cnt = g_cnt[d];
        int off = g_off[d];
        float m = NEGINF;
        for (int base = 0; base < cnt; base += 32) {
            int rem = cnt - base;
            int si = (lane < rem) ? g_ssrc[off + base + lane] : 0;
            int lim = rem < 32 ? rem : 32;
            int j = 0;
            for (; j + 4 <= lim; j += 4) {
                int s0 = __shfl_sync(0xffffffffu, si, j);
                int s1 = __shfl_sync(0xffffffffu, si, j + 1);
                int s2 = __shfl_sync(0xffffffffu, si, j + 2);
                int s3 = __shfl_sync(0xffffffffu, si, j + 3);
                float v0 = g_B[s0 * 32 + lane];
                float v1 = g_B[s1 * 32 + lane];
                float v2 = g_B[s2 * 32 + lane];
                float v3 = g_B[s3 * 32 + lane];
                m = fmaxf(m, fmaxf(fmaxf(v0, v1), fmaxf(v2, v3)));
            }
            for (; j < lim; j++) {
                int sj = __shfl_sync(0xffffffffu, si, j);
                m = fmaxf(m, g_B[sj * 32 + lane]);
            }
        }
        float a = g_A[d * 32 + lane];
        float val = (cnt > 0) ? (a + m) : 0.f;
        g_agg[d * 32 + lane] = val;
        s += val; q += val * val;
    }

    atomicAdd(&ss[lane], s);
    atomicAdd(&sq[lane], q);
    __syncthreads();
    if (threadIdx.x < 32) {
        atomicAdd(&g_stats[64 + threadIdx.x], (double)ss[threadIdx.x]);
        atomicAdd(&g_stats[96 + threadIdx.x], (double)sq[threadIdx.x]);
    }
}

// ---------------- K7: BN1(emb) + BN2(agg) + output MLP ----------------
__global__ void k_final(const float* __restrict__ ga, const float* __restrict__ bea,
                        const float* __restrict__ gc, const float* __restrict__ bec,
                        const float* __restrict__ W1, const float* __restrict__ b1,
                        const float* __restrict__ W2, const float* __restrict__ b2,
                        float* __restrict__ out) {
    __shared__ float sW1[512], sb1[16], sW2[16];
    __shared__ float sc1[32], sh1[32], sc2[32], sh2[32];
    __shared__ float sb2;
    int tid = threadIdx.x;
    for (int i = tid; i < 512; i += blockDim.x) sW1[i] = W1[i];
    if (tid < 16) { sb1[tid] = b1[tid]; sW2[tid] = W2[tid]; }
    if (tid == 0) sb2 = b2[0];
    if (tid < 32) {
        double mu1  = g_stats[tid] * (1.0 / NN);
        double var1 = g_stats[32 + tid] * (1.0 / NN) - mu1 * mu1;
        float i1 = rsqrtf((float)var1 + 1e-5f) * ga[tid];
        sc1[tid] = i1;
        sh1[tid] = bea[tid] - (float)mu1 * i1;
        double mu2  = g_stats[64 + tid] * (1.0 / NN);
        double var2 = g_stats[96 + tid] * (1.0 / NN) - mu2 * mu2;
        float i2 = rsqrtf((float)var2 + 1e-5f) * gc[tid];
        sc2[tid] = i2;
        sh2[tid] = bec[tid] - (float)mu2 * i2;
    }
    __syncthreads();

    int n = blockIdx.x * blockDim.x + tid;
    if (n >= NN) return;

    float ef[32];
#pragma unroll
    for (int j = 0; j < 32; j += 4) {
        float4 e = *(const float4*)&g_emb[n * 32 + j];
        float4 a = *(const float4*)&g_agg[n * 32 + j];
        ef[j]     = e.x * sc1[j]     + sh1[j]     + a.x * sc2[j]     + sh2[j];
        ef[j + 1] = e.y * sc1[j + 1] + sh1[j + 1] + a.y * sc2[j + 1] + sh2[j + 1];
        ef[j + 2] = e.z * sc1[j + 2] + sh1[j + 2] + a.z * sc2[j + 2] + sh2[j + 2];
        ef[j + 3] = e.w * sc1[j + 3] + sh1[j + 3] + a.w * sc2[j + 3] + sh2[j + 3];
    }

    float o = sb2;
#pragma unroll
    for (int h4 = 0; h4 < 16; h4 += 4) {
        unsigned long long aL = pk2(sb1[h4], sb1[h4 + 1]);
        unsigned long long aH = pk2(sb1[h4 + 2], sb1[h4 + 3]);
#pragma unroll
        for (int j = 0; j < 32; j++) {
            float4 w = *(const float4*)&sW1[j * 16 + h4];
            unsigned long long e2 = pk2(ef[j], ef[j]);
            aL = fma2(e2, pk2(w.x, w.y), aL);
            aH = fma2(e2, pk2(w.z, w.w), aH);
        }
        float v0, v1, v2, v3;
        upk2(aL, v0, v1); upk2(aH, v2, v3);
        o += eluf(v0) * sW2[h4] + eluf(v1) * sW2[h4 + 1]
           + eluf(v2) * sW2[h4 + 2] + eluf(v3) * sW2[h4 + 3];
    }
    out[n] = o;
}

// ---------------- launch ----------------
extern "C" void kernel_launch(void* const* d_in, const int* in_sizes, int n_in,
                              void* d_out, int out_size) {
    const float* x_cont = (const float*)d_in[0];
    const int*   x_cat  = (const int*)d_in[1];
    const int*   eidx   = (const int*)d_in[2];
    const float* W_cont = (const float*)d_in[4];
    const float* b_cont = (const float*)d_in[5];
    const float* T_chrg = (const float*)d_in[6];
    const float* T_pdg  = (const float*)d_in[7];
    const float* T_pv   = (const float*)d_in[8];
    const float* W_cat  = (const float*)d_in[9];
    const float* b_cat  = (const float*)d_in[10];
    const float* W_enc  = (const float*)d_in[11];
    const float* b_enc  = (const float*)d_in[12];
    const float* g_all  = (const float*)d_in[13];
    const float* be_all = (const float*)d_in[14];
    const float* W_msg  = (const float*)d_in[15];
    const float* b_msg  = (const float*)d_in[16];
    const float* g_conv = (const float*)d_in[17];
    const float* be_conv= (const float*)d_in[18];
    const float* W_out1 = (const float*)d_in[19];
    const float* b_out1 = (const float*)d_in[20];
    const float* W_out2 = (const float*)d_in[21];
    const float* b_out2 = (const float*)d_in[22];
    float* out = (float*)d_out;

    const int TB = 256;
    const int nodeBlocks = (NN + TB - 1) / TB;
    const int edgeBlocks = (EE + TB - 1) / TB;

    k_init<<<SCAN_B, SCAN_T>>>();
    k_encode<<<nodeBlocks, TB>>>(x_cont, x_cat, W_cont, b_cont, T_chrg, T_pdg, T_pv,
                                 W_cat, b_cat, W_enc, b_enc);
    k_hist<<<edgeBlocks, TB>>>(eidx);
    k_scan_a<<<SCAN_B, SCAN_T>>>();
    k_scan_b<<<1, 32>>>();
    k_scan_c<<<SCAN_B, SCAN_T>>>();
    k_scatter<<<edgeBlocks, TB>>>(eidx);
    k_stats0<<<512, TB>>>();
    k_node2<<<nodeBlocks, TB>>>(g_all, be_all, W_msg, b_msg);
    k_segmax<<<nodeBlocks, TB>>>();
    k_final<<<nodeBlocks, TB>>>(g_all, be_all, g_conv, be_conv,
                                W_out1, b_out1, W_out2, b_out2, out);
}